// round 5
// baseline (speedup 1.0000x reference)
#include <cuda_runtime.h>

#define NB   2
#define SEQ  2048
#define DIM  1024
#define NH   16
#define HD   64
#define MTOT (NB * SEQ)   // 4096

// ---- scratch (no allocations allowed; __device__ globals are the sanctioned path) ----
__device__ float g_Q[NB * NH * SEQ * HD];   // [b][h][s][d]
__device__ float g_K[NB * NH * SEQ * HD];
__device__ float g_V[NB * NH * SEQ * HD];
__device__ float g_O[NB * SEQ * DIM];       // merged-head attention output [b][s][h*64+d]

// ---------------------------------------------------------------------------
// Fast expf on the FMA/ALU pipes (avoids the MUFU bottleneck: rt=8/SMSP).
// Valid for softmax args (x <= 0). rel err ~3e-6.
// ---------------------------------------------------------------------------
__device__ __forceinline__ float fexp(float x) {
    x = fmaxf(x, -87.0f);
    float t = x * 1.4426950408889634f;          // x * log2(e)
    float r = t + 12582912.0f;                  // round-to-nearest via 1.5*2^23
    int   n = __float_as_int(r) - 0x4B400000;   // integer part
    float f = t - (r - 12582912.0f);            // fractional part in [-0.5, 0.5]
    float p = 1.33335581464e-3f;
    p = fmaf(p, f, 9.61812910763e-3f);
    p = fmaf(p, f, 5.55041086648e-2f);
    p = fmaf(p, f, 2.40226506959e-1f);
    p = fmaf(p, f, 6.93147180560e-1f);
    p = fmaf(p, f, 1.0f);
    return __int_as_float(__float_as_int(p) + (n << 23));   // p * 2^n
}

// ---------------------------------------------------------------------------
// SGEMM: C[M x N] = A[M x 1024] * W[1024 x N] + bias
// BM=BN=128, BK=16, 256 threads, 8x8 microtiles.
// Ping-pong double-buffered smem; ONE barrier per K-slab.
// Epilogue fully vectorized (STG.128): each thread's 8-wide n-run is
// contiguous in the destination for both EPI variants.
// EPI==0: QKV epilogue, scatters into g_Q/g_K/g_V in [b][h][s][d] layout.
// EPI==1: plain epilogue into Cout (A is taken from g_O).
// ---------------------------------------------------------------------------
template <int N, int EPI>
__global__ void __launch_bounds__(256)
gemm_kernel(const float* __restrict__ A, const float* __restrict__ W,
            const float* __restrict__ bias, float* __restrict__ Cout)
{
    __shared__ float As[2][16][132];   // transposed A tile: As[buf][k][m]
    __shared__ float Bs[2][16][128];   // Bs[buf][k][n]

    const int tid = threadIdx.x;
    const int tr  = tid >> 4;       // 0..15
    const int tc  = tid & 15;       // 0..15
    const int m0  = blockIdx.y * 128;
    const int n0  = blockIdx.x * 128;

    const float* __restrict__ Ap = (EPI == 1) ? (const float*)g_O : A;

    // per-thread load indices (2 float4 each for A and B per slab)
    const int a_row0 = tid >> 2;             // A: row, f4
    const int a_f4   = tid & 3;
    const int b_row0 = tid >> 5;             // B: row 0..7 (+8), f4 0..31
    const int b_f4   = tid & 31;

    float acc[8][8];
#pragma unroll
    for (int i = 0; i < 8; i++)
#pragma unroll
        for (int j = 0; j < 8; j++) acc[i][j] = 0.0f;

    float4 ar0, ar1, br0, br1;

    // ---- preload slab k0=0 into buffer 0 ----
    ar0 = *(const float4*)(Ap + (size_t)(m0 + a_row0)      * DIM + a_f4 * 4);
    ar1 = *(const float4*)(Ap + (size_t)(m0 + a_row0 + 64) * DIM + a_f4 * 4);
    br0 = *(const float4*)(W + (size_t)(b_row0)     * N + n0 + b_f4 * 4);
    br1 = *(const float4*)(W + (size_t)(b_row0 + 8) * N + n0 + b_f4 * 4);
    As[0][a_f4 * 4 + 0][a_row0]      = ar0.x;
    As[0][a_f4 * 4 + 1][a_row0]      = ar0.y;
    As[0][a_f4 * 4 + 2][a_row0]      = ar0.z;
    As[0][a_f4 * 4 + 3][a_row0]      = ar0.w;
    As[0][a_f4 * 4 + 0][a_row0 + 64] = ar1.x;
    As[0][a_f4 * 4 + 1][a_row0 + 64] = ar1.y;
    As[0][a_f4 * 4 + 2][a_row0 + 64] = ar1.z;
    As[0][a_f4 * 4 + 3][a_row0 + 64] = ar1.w;
    *(float4*)&Bs[0][b_row0][b_f4 * 4]     = br0;
    *(float4*)&Bs[0][b_row0 + 8][b_f4 * 4] = br1;
    __syncthreads();

    int cur = 0;
    for (int k0 = 0; k0 < DIM; k0 += 16) {
        const int  knxt = k0 + 16;
        const bool has  = (knxt < DIM);

        // issue next-slab global loads early (latency hidden behind compute)
        if (has) {
            ar0 = *(const float4*)(Ap + (size_t)(m0 + a_row0)      * DIM + knxt + a_f4 * 4);
            ar1 = *(const float4*)(Ap + (size_t)(m0 + a_row0 + 64) * DIM + knxt + a_f4 * 4);
            br0 = *(const float4*)(W + (size_t)(knxt + b_row0)     * N + n0 + b_f4 * 4);
            br1 = *(const float4*)(W + (size_t)(knxt + b_row0 + 8) * N + n0 + b_f4 * 4);
        }

        // compute on current buffer
#pragma unroll
        for (int k = 0; k < 16; k++) {
            float a[8], b[8];
            *(float4*)&a[0] = *(const float4*)&As[cur][k][tr * 8];
            *(float4*)&a[4] = *(const float4*)&As[cur][k][tr * 8 + 4];
            *(float4*)&b[0] = *(const float4*)&Bs[cur][k][tc * 8];
            *(float4*)&b[4] = *(const float4*)&Bs[cur][k][tc * 8 + 4];
#pragma unroll
            for (int i = 0; i < 8; i++)
#pragma unroll
                for (int j = 0; j < 8; j++)
                    acc[i][j] = fmaf(a[i], b[j], acc[i][j]);
        }

        // store next slab into the alternate buffer (nobody reads it yet)
        if (has) {
            const int nb = cur ^ 1;
            As[nb][a_f4 * 4 + 0][a_row0]      = ar0.x;
            As[nb][a_f4 * 4 + 1][a_row0]      = ar0.y;
            As[nb][a_f4 * 4 + 2][a_row0]      = ar0.z;
            As[nb][a_f4 * 4 + 3][a_row0]      = ar0.w;
            As[nb][a_f4 * 4 + 0][a_row0 + 64] = ar1.x;
            As[nb][a_f4 * 4 + 1][a_row0 + 64] = ar1.y;
            As[nb][a_f4 * 4 + 2][a_row0 + 64] = ar1.z;
            As[nb][a_f4 * 4 + 3][a_row0 + 64] = ar1.w;
            *(float4*)&Bs[nb][b_row0][b_f4 * 4]     = br0;
            *(float4*)&Bs[nb][b_row0 + 8][b_f4 * 4] = br1;
            __syncthreads();
            cur = nb;
        }
    }

    // ---- epilogue (vectorized: two float4 stores per row) ----
    const int nbase = n0 + tc * 8;
    float4 bv0 = *(const float4*)(bias + nbase);
    float4 bv1 = *(const float4*)(bias + nbase + 4);

    // destination base for the 8-wide contiguous n-run
    float* dst8;
    size_t row_stride;            // elements between consecutive m for this run
    if (EPI == 0) {
        const int which = nbase >> 10;           // 0=q 1=k 2=v (constant over run)
        const int rr    = nbase & 1023;
        const int h     = rr >> 6;
        const int d     = rr & 63;               // d..d+7 within one head
        float* base = (which == 0) ? g_Q : (which == 1) ? g_K : g_V;
        const int b_ = m0 >> 11;                 // all 8 rows share b_ (m-block of 128)
        const int s0 = (m0 & 2047) + tr * 8;
        dst8 = base + (((size_t)(b_ * NH + h)) * SEQ + s0) * HD + d;
        row_stride = HD;
    } else {
        dst8 = Cout + (size_t)(m0 + tr * 8) * DIM + nbase;
        row_stride = DIM;
    }

#pragma unroll
    for (int i = 0; i < 8; i++) {
        float4 v0 = make_float4(acc[i][0] + bv0.x, acc[i][1] + bv0.y,
                                acc[i][2] + bv0.z, acc[i][3] + bv0.w);
        float4 v1 = make_float4(acc[i][4] + bv1.x, acc[i][5] + bv1.y,
                                acc[i][6] + bv1.z, acc[i][7] + bv1.w);
        *(float4*)(dst8 + (size_t)i * row_stride)     = v0;
        *(float4*)(dst8 + (size_t)i * row_stride + 4) = v1;
    }
}

// ---------------------------------------------------------------------------
// Flash attention, fp32, causal. BR = BC = 128, 256 threads (16x16).
// Q/K stored transposed in smem ([d][i], padded pitch 132) so QK^T microtile
// A-frags are warp-broadcast. P stored transposed ([j][i]) for the PV GEMM.
// Online-softmax state (m, l) lives in registers: each tile row is owned by
// the 16 lanes of one half-warp -> width-16 shfl reductions.
// LPT scheduling: heavy q-tiles (more K iterations) launch FIRST so the
// last wave drains light blocks, not 16-iteration ones.
// ---------------------------------------------------------------------------
#define FL_SMEM_FLOATS (64 * 132 * 2 + 128 * 68 + 128 * 132)
#define FL_SMEM_BYTES  (FL_SMEM_FLOATS * 4)

__global__ void __launch_bounds__(256, 1) attn_kernel()
{
    extern __shared__ float sm[];
    float* Qt = sm;                      // [64][132]  (d-major, 128 q rows)
    float* Kt = Qt + 64 * 132;           // [64][132]  (d-major, 128 k rows)
    float* Vs = Kt + 64 * 132;           // [128][68]  (row-major V tile)
    float* Pt = Vs + 128 * 68;           // [128][132] (P transposed: [j][i])

    const int tid = threadIdx.x;
    const int tr  = tid >> 4;            // 0..15
    const int tc  = tid & 15;            // 0..15
    const int qt  = gridDim.x - 1 - blockIdx.x;   // LPT: heavy tiles first
    const int bh  = blockIdx.y;          // b*H + h
    const int q0  = qt * 128;

    const float* __restrict__ Qg = g_Q + (size_t)bh * SEQ * HD;
    const float* __restrict__ Kg = g_K + (size_t)bh * SEQ * HD;
    const float* __restrict__ Vg = g_V + (size_t)bh * SEQ * HD;

    // load Q tile transposed
    {
        int rbase = tid >> 4;
        int f4    = tid & 15;
#pragma unroll
        for (int p = 0; p < 8; p++) {
            int r = rbase + p * 16;
            float4 v = *(const float4*)(Qg + (size_t)(q0 + r) * HD + f4 * 4);
            Qt[(f4 * 4 + 0) * 132 + r] = v.x;
            Qt[(f4 * 4 + 1) * 132 + r] = v.y;
            Qt[(f4 * 4 + 2) * 132 + r] = v.z;
            Qt[(f4 * 4 + 3) * 132 + r] = v.w;
        }
    }

    float m_i[8], l_i[8], o_acc[8][4];
#pragma unroll
    for (int i = 0; i < 8; i++) {
        m_i[i] = -1e30f;
        l_i[i] = 0.0f;
#pragma unroll
        for (int c = 0; c < 4; c++) o_acc[i][c] = 0.0f;
    }

    for (int kt = 0; kt <= qt; kt++) {
        __syncthreads();   // protect K/V/P reuse from previous iteration
        // load K (transposed) and V tiles
        {
            int rbase = tid >> 4;
            int f4    = tid & 15;
#pragma unroll
            for (int p = 0; p < 8; p++) {
                int r = rbase + p * 16;
                float4 v = *(const float4*)(Kg + (size_t)(kt * 128 + r) * HD + f4 * 4);
                Kt[(f4 * 4 + 0) * 132 + r] = v.x;
                Kt[(f4 * 4 + 1) * 132 + r] = v.y;
                Kt[(f4 * 4 + 2) * 132 + r] = v.z;
                Kt[(f4 * 4 + 3) * 132 + r] = v.w;
                float4 w = *(const float4*)(Vg + (size_t)(kt * 128 + r) * HD + f4 * 4);
                *(float4*)&Vs[r * 68 + f4 * 4] = w;
            }
        }
        __syncthreads();

        // S = Q K^T  (each thread: 8x8 of the 128x128 tile)
        float s_acc[8][8];
#pragma unroll
        for (int i = 0; i < 8; i++)
#pragma unroll
            for (int j = 0; j < 8; j++) s_acc[i][j] = 0.0f;

#pragma unroll 4
        for (int d = 0; d < 64; d++) {
            float a[8], b[8];
            *(float4*)&a[0] = *(const float4*)&Qt[d * 132 + tr * 8];
            *(float4*)&a[4] = *(const float4*)&Qt[d * 132 + tr * 8 + 4];
            *(float4*)&b[0] = *(const float4*)&Kt[d * 132 + tc * 8];
            *(float4*)&b[4] = *(const float4*)&Kt[d * 132 + tc * 8 + 4];
#pragma unroll
            for (int i = 0; i < 8; i++)
#pragma unroll
                for (int j = 0; j < 8; j++)
                    s_acc[i][j] = fmaf(a[i], b[j], s_acc[i][j]);
        }

        // scale + causal mask (only the diagonal tile needs per-element mask)
        const bool diag = (kt == qt);
#pragma unroll
        for (int i = 0; i < 8; i++)
#pragma unroll
            for (int j = 0; j < 8; j++) {
                float sv = s_acc[i][j] * 0.125f;   // 1/sqrt(64)
                if (diag && (tc * 8 + j > tr * 8 + i)) sv = -1e30f;
                s_acc[i][j] = sv;
            }

        // online softmax (row = 16 lanes of one half-warp)
#pragma unroll
        for (int i = 0; i < 8; i++) {
            float tmax = s_acc[i][0];
#pragma unroll
            for (int j = 1; j < 8; j++) tmax = fmaxf(tmax, s_acc[i][j]);
#pragma unroll
            for (int o = 8; o > 0; o >>= 1)
                tmax = fmaxf(tmax, __shfl_xor_sync(0xffffffffu, tmax, o, 16));
            float mnew = fmaxf(m_i[i], tmax);
            float corr = fexp(m_i[i] - mnew);
            m_i[i] = mnew;
            float ps = 0.0f;
#pragma unroll
            for (int j = 0; j < 8; j++) {
                float pv = fexp(s_acc[i][j] - mnew);
                s_acc[i][j] = pv;
                ps += pv;
            }
#pragma unroll
            for (int o = 8; o > 0; o >>= 1)
                ps += __shfl_xor_sync(0xffffffffu, ps, o, 16);
            l_i[i] = l_i[i] * corr + ps;
#pragma unroll
            for (int c = 0; c < 4; c++) o_acc[i][c] *= corr;
        }

        // store P transposed: Pt[j][i]
#pragma unroll
        for (int j = 0; j < 8; j++) {
            float4 v0 = make_float4(s_acc[0][j], s_acc[1][j], s_acc[2][j], s_acc[3][j]);
            float4 v1 = make_float4(s_acc[4][j], s_acc[5][j], s_acc[6][j], s_acc[7][j]);
            *(float4*)&Pt[(tc * 8 + j) * 132 + tr * 8]     = v0;
            *(float4*)&Pt[(tc * 8 + j) * 132 + tr * 8 + 4] = v1;
        }
        __syncthreads();

        // O += P @ V   (each thread: 8 rows x 4 cols of the 128x64 tile)
#pragma unroll 4
        for (int j = 0; j < 128; j++) {
            float a[8];
            *(float4*)&a[0] = *(const float4*)&Pt[j * 132 + tr * 8];
            *(float4*)&a[4] = *(const float4*)&Pt[j * 132 + tr * 8 + 4];
            float4 bv = *(const float4*)&Vs[j * 68 + tc * 4];
#pragma unroll
            for (int i = 0; i < 8; i++) {
                o_acc[i][0] = fmaf(a[i], bv.x, o_acc[i][0]);
                o_acc[i][1] = fmaf(a[i], bv.y, o_acc[i][1]);
                o_acc[i][2] = fmaf(a[i], bv.z, o_acc[i][2]);
                o_acc[i][3] = fmaf(a[i], bv.w, o_acc[i][3]);
            }
        }
    }

    // epilogue: normalize and write merged-head layout [b][s][h*64+c]
    const int b_ = bh / NH;
    const int h  = bh % NH;
#pragma unroll
    for (int i = 0; i < 8; i++) {
        float inv = 1.0f / l_i[i];
        int row = q0 + tr * 8 + i;
        float4 v = make_float4(o_acc[i][0] * inv, o_acc[i][1] * inv,
                               o_acc[i][2] * inv, o_acc[i][3] * inv);
        *(float4*)(g_O + ((size_t)(b_ * SEQ) + row) * DIM + h * HD + tc * 4) = v;
    }
}

// ---------------------------------------------------------------------------
extern "C" void kernel_launch(void* const* d_in, const int* in_sizes, int n_in,
                              void* d_out, int out_size)
{
    const float* hs     = (const float*)d_in[0];
    const float* W_attn = (const float*)d_in[1];
    const float* b_attn = (const float*)d_in[2];
    const float* W_proj = (const float*)d_in[3];
    const float* b_proj = (const float*)d_in[4];
    float* out = (float*)d_out;

    cudaFuncSetAttribute(attn_kernel,
                         cudaFuncAttributeMaxDynamicSharedMemorySize, FL_SMEM_BYTES);

    // 1) QKV projection, scattered into per-head layout
    gemm_kernel<3 * DIM, 0><<<dim3((3 * DIM) / 128, MTOT / 128), 256>>>(
        hs, W_attn, b_attn, nullptr);

    // 2) causal flash attention (LPT block order inside the kernel)
    attn_kernel<<<dim3(SEQ / 128, NB * NH), 256, FL_SMEM_BYTES>>>();

    // 3) output projection
    gemm_kernel<DIM, 1><<<dim3(DIM / 128, MTOT / 128), 256>>>(
        nullptr, W_proj, b_proj, out);
}

// round 13
// speedup vs baseline: 1.4583x; 1.4583x over previous
#include <cuda_runtime.h>
#include <cuda_bf16.h>
#include <cstdint>

#define NB   2
#define SEQ  2048
#define DIM  1024
#define NH   16
#define HD   64
#define MTOT (NB * SEQ)   // 4096
#define GK   DIM

// ---- scratch (__device__ globals; no allocations allowed) ----
__device__ float g_Q[NB * NH * SEQ * HD];
__device__ float g_K[NB * NH * SEQ * HD];
__device__ float g_V[NB * NH * SEQ * HD];
__device__ float g_O[NB * SEQ * DIM];

// weights transposed+split to bf16 hi/lo, [n][k]
__device__ __nv_bfloat16 g_WaT_hi[3 * DIM * DIM];
__device__ __nv_bfloat16 g_WaT_lo[3 * DIM * DIM];
__device__ __nv_bfloat16 g_WpT_hi[DIM * DIM];
__device__ __nv_bfloat16 g_WpT_lo[DIM * DIM];
// activations split to bf16 hi/lo, [m][k] (reused for hs then g_O)
__device__ __nv_bfloat16 g_Ah[MTOT * DIM];
__device__ __nv_bfloat16 g_Al[MTOT * DIM];

// ===========================================================================
__device__ __forceinline__ uint32_t smem_u32(const void* p) {
    uint32_t a;
    asm("{ .reg .u64 t; cvta.to.shared.u64 t, %1; cvt.u32.u64 %0, t; }"
        : "=r"(a) : "l"(p));
    return a;
}
#define CP_ASYNC16(dst, src) \
    asm volatile("cp.async.cg.shared.global [%0], [%1], 16;" \
                 :: "r"(dst), "l"(src) : "memory")
#define CP_COMMIT() asm volatile("cp.async.commit_group;" ::: "memory")

__device__ __forceinline__ void ldsm_x4(uint32_t (&r)[4], uint32_t addr) {
    asm volatile("ldmatrix.sync.aligned.m8n8.x4.shared.b16 {%0,%1,%2,%3}, [%4];"
                 : "=r"(r[0]), "=r"(r[1]), "=r"(r[2]), "=r"(r[3]) : "r"(addr));
}
__device__ __forceinline__ void mma_bf16(float (&c)[4], const uint32_t (&a)[4],
                                         uint32_t b0, uint32_t b1) {
    asm volatile(
        "mma.sync.aligned.m16n8k16.row.col.f32.bf16.bf16.f32 "
        "{%0,%1,%2,%3}, {%4,%5,%6,%7}, {%8,%9}, {%0,%1,%2,%3};"
        : "+f"(c[0]), "+f"(c[1]), "+f"(c[2]), "+f"(c[3])
        : "r"(a[0]), "r"(a[1]), "r"(a[2]), "r"(a[3]), "r"(b0), "r"(b1));
}

// fast expf on FMA/ALU pipes (softmax args <= 0)
__device__ __forceinline__ float fexp(float x) {
    x = fmaxf(x, -87.0f);
    float t = x * 1.4426950408889634f;
    float r = t + 12582912.0f;
    int   n = __float_as_int(r) - 0x4B400000;
    float f = t - (r - 12582912.0f);
    float p = 1.33335581464e-3f;
    p = fmaf(p, f, 9.61812910763e-3f);
    p = fmaf(p, f, 5.55041086648e-2f);
    p = fmaf(p, f, 2.40226506959e-1f);
    p = fmaf(p, f, 6.93147180560e-1f);
    p = fmaf(p, f, 1.0f);
    return __int_as_float(__float_as_int(p) + (n << 23));
}

// ===========================================================================
// weight transpose + split: W[K x Ncols] -> Th/Tl[Ncols x K]
// ===========================================================================
template <int WSEL>
__global__ void __launch_bounds__(256)
transpose_split(const float* __restrict__ W, int Ncols)
{
    __shared__ float t[32][33];
    __nv_bfloat16* Th = (WSEL == 0) ? g_WaT_hi : g_WpT_hi;
    __nv_bfloat16* Tl = (WSEL == 0) ? g_WaT_lo : g_WpT_lo;
    const int n0 = blockIdx.x * 32, k0 = blockIdx.y * 32;
    const int tx = threadIdx.x, ty = threadIdx.y;
#pragma unroll
    for (int j = ty; j < 32; j += 8)
        t[j][tx] = W[(size_t)(k0 + j) * Ncols + n0 + tx];
    __syncthreads();
#pragma unroll
    for (int j = ty; j < 32; j += 8) {
        float x = t[tx][j];
        __nv_bfloat16 h = __float2bfloat16_rn(x);
        __nv_bfloat16 l = __float2bfloat16_rn(x - __bfloat162float(h));
        Th[(size_t)(n0 + j) * GK + k0 + tx] = h;
        Tl[(size_t)(n0 + j) * GK + k0 + tx] = l;
    }
}

// ===========================================================================
// activation split: X[M x 1024] fp32 -> g_Ah/g_Al bf16. SRC=1 reads g_O.
// ===========================================================================
template <int SRC>
__global__ void __launch_bounds__(256)
split_act(const float* __restrict__ X)
{
    const float* src = (SRC == 1) ? (const float*)g_O : X;
    const size_t base = (size_t)blockIdx.x * DIM + threadIdx.x * 4;
    float4 v = *(const float4*)(src + base);
    __nv_bfloat16 h0 = __float2bfloat16_rn(v.x);
    __nv_bfloat16 h1 = __float2bfloat16_rn(v.y);
    __nv_bfloat16 h2 = __float2bfloat16_rn(v.z);
    __nv_bfloat16 h3 = __float2bfloat16_rn(v.w);
    __nv_bfloat16 l0 = __float2bfloat16_rn(v.x - __bfloat162float(h0));
    __nv_bfloat16 l1 = __float2bfloat16_rn(v.y - __bfloat162float(h1));
    __nv_bfloat16 l2 = __float2bfloat16_rn(v.z - __bfloat162float(h2));
    __nv_bfloat16 l3 = __float2bfloat16_rn(v.w - __bfloat162float(h3));
    ushort4 H = make_ushort4(__bfloat16_as_ushort(h0), __bfloat16_as_ushort(h1),
                             __bfloat16_as_ushort(h2), __bfloat16_as_ushort(h3));
    ushort4 L = make_ushort4(__bfloat16_as_ushort(l0), __bfloat16_as_ushort(l1),
                             __bfloat16_as_ushort(l2), __bfloat16_as_ushort(l3));
    *(ushort4*)(g_Ah + base) = H;
    *(ushort4*)(g_Al + base) = L;
}

// ===========================================================================
// mma.sync GEMM: C[M x NTOT] = A * W + bias, bf16 2-term split, fp32 acc.
// 128x128 tile, BK=32, 8 warps (4m x 2n), warp tile 32x64 (m16n8k16 frags).
// cp.async double-buffered smem (pitch 40 bf16 = conflict-free ldmatrix).
// ===========================================================================
#define PITCHB    80                 // bytes per smem row (40 bf16)
#define ARR_BYTES (128 * PITCHB)     // 10240
#define SLAB_BYTES (4 * ARR_BYTES)   // A_hi, A_lo, B_hi, B_lo
#define MMA_SMEM  (2 * SLAB_BYTES)   // 81920

template <int NTOT, int EPI>
__global__ void __launch_bounds__(256)
mma_gemm(const float* __restrict__ bias, float* __restrict__ Cout)
{
    extern __shared__ char smem[];
    const uint32_t sb = smem_u32(smem);
    const int tid  = threadIdx.x;
    const int wid  = tid >> 5;
    const int lane = tid & 31;
    const int m0   = blockIdx.y * 128;
    const int n0   = blockIdx.x * 128;

    const __nv_bfloat16* __restrict__ Bh = EPI ? g_WpT_hi : g_WaT_hi;
    const __nv_bfloat16* __restrict__ Bl = EPI ? g_WpT_lo : g_WaT_lo;

    // cp.async per-thread coords: 2 chunks of 16B per array per slab
    const int ch_row0 = tid >> 2;            // chunk p=0: row, p=1: row+64
    const int ch_ke   = (tid & 3) * 8;       // k element offset within slab

    auto issue = [&](int s, int b) {
        const int k0 = s * 32;
#pragma unroll
        for (int p = 0; p < 2; p++) {
            const int row = ch_row0 + p * 64;
            const uint32_t d = sb + b * SLAB_BYTES + row * PITCHB + ch_ke * 2;
            CP_ASYNC16(d + 0 * ARR_BYTES, g_Ah + (size_t)(m0 + row) * GK + k0 + ch_ke);
            CP_ASYNC16(d + 1 * ARR_BYTES, g_Al + (size_t)(m0 + row) * GK + k0 + ch_ke);
            CP_ASYNC16(d + 2 * ARR_BYTES, Bh   + (size_t)(n0 + row) * GK + k0 + ch_ke);
            CP_ASYNC16(d + 3 * ARR_BYTES, Bl   + (size_t)(n0 + row) * GK + k0 + ch_ke);
        }
        CP_COMMIT();
    };

    // fragment lane addressing
    const int mbase = (wid >> 1) * 32;
    const int nbase = (wid & 1) * 64;
    const int a_r = lane & 15;
    const int a_k = (lane >> 4) * 8;
    const int b_r = (lane & 7) + ((lane >> 4) << 3);
    const int b_k = (lane & 8) ? 8 : 0;

    float acc[2][8][4];
#pragma unroll
    for (int mt = 0; mt < 2; mt++)
#pragma unroll
        for (int nt = 0; nt < 8; nt++)
#pragma unroll
            for (int q = 0; q < 4; q++) acc[mt][nt][q] = 0.0f;

    issue(0, 0);
    for (int s = 0; s < 32; s++) {
        const int b = s & 1;
        if (s + 1 < 32) {
            issue(s + 1, b ^ 1);
            asm volatile("cp.async.wait_group 1;" ::: "memory");
        } else {
            asm volatile("cp.async.wait_group 0;" ::: "memory");
        }
        __syncthreads();

        const uint32_t bufb = sb + b * SLAB_BYTES;
#pragma unroll
        for (int ks = 0; ks < 2; ks++) {
            uint32_t ah[2][4], al_[2][4];
#pragma unroll
            for (int mt = 0; mt < 2; mt++) {
                const uint32_t ao = (mbase + mt * 16 + a_r) * PITCHB + (ks * 16 + a_k) * 2;
                ldsm_x4(ah[mt],  bufb + 0 * ARR_BYTES + ao);
                ldsm_x4(al_[mt], bufb + 1 * ARR_BYTES + ao);
            }
#pragma unroll
            for (int np = 0; np < 4; np++) {
                uint32_t bh4[4], bl4[4];
                const uint32_t bo = (nbase + np * 16 + b_r) * PITCHB + (ks * 16 + b_k) * 2;
                ldsm_x4(bh4, bufb + 2 * ARR_BYTES + bo);
                ldsm_x4(bl4, bufb + 3 * ARR_BYTES + bo);
#pragma unroll
                for (int mt = 0; mt < 2; mt++) {
                    mma_bf16(acc[mt][np * 2],     ah[mt],  bh4[0], bh4[1]);
                    mma_bf16(acc[mt][np * 2],     ah[mt],  bl4[0], bl4[1]);
                    mma_bf16(acc[mt][np * 2],     al_[mt], bh4[0], bh4[1]);
                    mma_bf16(acc[mt][np * 2 + 1], ah[mt],  bh4[2], bh4[3]);
                    mma_bf16(acc[mt][np * 2 + 1], ah[mt],  bl4[2], bl4[3]);
                    mma_bf16(acc[mt][np * 2 + 1], al_[mt], bh4[2], bh4[3]);
                }
            }
        }
        __syncthreads();
    }

    // ---- epilogue ----
    const int qrow = lane >> 2;          // 0..7
    const int qcol = (lane & 3) * 2;
    // EPI==0: whole CTA shares `which` (n0 is 128-aligned, 128 | 1024)
    float* qkv_base = nullptr;
    if (EPI == 0) {
        const int which = n0 >> 10;
        qkv_base = (which == 0) ? g_Q : (which == 1) ? g_K : g_V;
    }

#pragma unroll
    for (int mt = 0; mt < 2; mt++) {
#pragma unroll
        for (int nt = 0; nt < 8; nt++) {
            const int n_g = n0 + nbase + nt * 8 + qcol;
            const float2 bv = *(const float2*)(bias + n_g);
            const int m_g = m0 + mbase + mt * 16 + qrow;
            float2 v0 = make_float2(acc[mt][nt][0] + bv.x, acc[mt][nt][1] + bv.y);
            float2 v1 = make_float2(acc[mt][nt][2] + bv.x, acc[mt][nt][3] + bv.y);
            if (EPI == 0) {
                const int rr = n_g & 1023;
                const int h  = rr >> 6;
                const int d  = rr & 63;
                const int b0_ = m_g >> 11, s0_ = m_g & 2047;
                const int b1_ = (m_g + 8) >> 11, s1_ = (m_g + 8) & 2047;
                *(float2*)(qkv_base + (((size_t)(b0_ * NH + h)) * SEQ + s0_) * HD + d) = v0;
                *(float2*)(qkv_base + (((size_t)(b1_ * NH + h)) * SEQ + s1_) * HD + d) = v1;
            } else {
                *(float2*)(Cout + (size_t)m_g * DIM + n_g)       = v0;
                *(float2*)(Cout + (size_t)(m_g + 8) * DIM + n_g) = v1;
            }
        }
    }
}

// ---------------------------------------------------------------------------
// Flash attention, fp32, causal (measured-correct round-5 version, LPT order)
// ---------------------------------------------------------------------------
#define FL_SMEM_FLOATS (64 * 132 * 2 + 128 * 68 + 128 * 132)
#define FL_SMEM_BYTES  (FL_SMEM_FLOATS * 4)

__global__ void __launch_bounds__(256, 1) attn_kernel()
{
    extern __shared__ float sm[];
    float* Qt = sm;
    float* Kt = Qt + 64 * 132;
    float* Vs = Kt + 64 * 132;
    float* Pt = Vs + 128 * 68;

    const int tid = threadIdx.x;
    const int tr  = tid >> 4;
    const int tc  = tid & 15;
    const int qt  = gridDim.x - 1 - blockIdx.x;
    const int bh  = blockIdx.y;
    const int q0  = qt * 128;

    const float* __restrict__ Qg = g_Q + (size_t)bh * SEQ * HD;
    const float* __restrict__ Kg = g_K + (size_t)bh * SEQ * HD;
    const float* __restrict__ Vg = g_V + (size_t)bh * SEQ * HD;

    {
        int rbase = tid >> 4;
        int f4    = tid & 15;
#pragma unroll
        for (int p = 0; p < 8; p++) {
            int r = rbase + p * 16;
            float4 v = *(const float4*)(Qg + (size_t)(q0 + r) * HD + f4 * 4);
            Qt[(f4 * 4 + 0) * 132 + r] = v.x;
            Qt[(f4 * 4 + 1) * 132 + r] = v.y;
            Qt[(f4 * 4 + 2) * 132 + r] = v.z;
            Qt[(f4 * 4 + 3) * 132 + r] = v.w;
        }
    }

    float m_i[8], l_i[8], o_acc[8][4];
#pragma unroll
    for (int i = 0; i < 8; i++) {
        m_i[i] = -1e30f;
        l_i[i] = 0.0f;
#pragma unroll
        for (int c = 0; c < 4; c++) o_acc[i][c] = 0.0f;
    }

    for (int kt = 0; kt <= qt; kt++) {
        __syncthreads();
        {
            int rbase = tid >> 4;
            int f4    = tid & 15;
#pragma unroll
            for (int p = 0; p < 8; p++) {
                int r = rbase + p * 16;
                float4 v = *(const float4*)(Kg + (size_t)(kt * 128 + r) * HD + f4 * 4);
                Kt[(f4 * 4 + 0) * 132 + r] = v.x;
                Kt[(f4 * 4 + 1) * 132 + r] = v.y;
                Kt[(f4 * 4 + 2) * 132 + r] = v.z;
                Kt[(f4 * 4 + 3) * 132 + r] = v.w;
                float4 w = *(const float4*)(Vg + (size_t)(kt * 128 + r) * HD + f4 * 4);
                *(float4*)&Vs[r * 68 + f4 * 4] = w;
            }
        }
        __syncthreads();

        float s_acc[8][8];
#pragma unroll
        for (int i = 0; i < 8; i++)
#pragma unroll
            for (int j = 0; j < 8; j++) s_acc[i][j] = 0.0f;

#pragma unroll 4
        for (int d = 0; d < 64; d++) {
            float a[8], b[8];
            *(float4*)&a[0] = *(const float4*)&Qt[d * 132 + tr * 8];
            *(float4*)&a[4] = *(const float4*)&Qt[d * 132 + tr * 8 + 4];
            *(float4*)&b[0] = *(const float4*)&Kt[d * 132 + tc * 8];
            *(float4*)&b[4] = *(const float4*)&Kt[d * 132 + tc * 8 + 4];
#pragma unroll
            for (int i = 0; i < 8; i++)
#pragma unroll
                for (int j = 0; j < 8; j++)
                    s_acc[i][j] = fmaf(a[i], b[j], s_acc[i][j]);
        }

        const bool diag = (kt == qt);
#pragma unroll
        for (int i = 0; i < 8; i++)
#pragma unroll
            for (int j = 0; j < 8; j++) {
                float sv = s_acc[i][j] * 0.125f;
                if (diag && (tc * 8 + j > tr * 8 + i)) sv = -1e30f;
                s_acc[i][j] = sv;
            }

#pragma unroll
        for (int i = 0; i < 8; i++) {
            float tmax = s_acc[i][0];
#pragma unroll
            for (int j = 1; j < 8; j++) tmax = fmaxf(tmax, s_acc[i][j]);
#pragma unroll
            for (int o = 8; o > 0; o >>= 1)
                tmax = fmaxf(tmax, __shfl_xor_sync(0xffffffffu, tmax, o, 16));
            float mnew = fmaxf(m_i[i], tmax);
            float corr = fexp(m_i[i] - mnew);
            m_i[i] = mnew;
            float ps = 0.0f;
#pragma unroll
            for (int j = 0; j < 8; j++) {
                float pv = fexp(s_acc[i][j] - mnew);
                s_acc[i][j] = pv;
                ps += pv;
            }
#pragma unroll
            for (int o = 8; o > 0; o >>= 1)
                ps += __shfl_xor_sync(0xffffffffu, ps, o, 16);
            l_i[i] = l_i[i] * corr + ps;
#pragma unroll
            for (int c = 0; c < 4; c++) o_acc[i][c] *= corr;
        }

#pragma unroll
        for (int j = 0; j < 8; j++) {
            float4 v0 = make_float4(s_acc[0][j], s_acc[1][j], s_acc[2][j], s_acc[3][j]);
            float4 v1 = make_float4(s_acc[4][j], s_acc[5][j], s_acc[6][j], s_acc[7][j]);
            *(float4*)&Pt[(tc * 8 + j) * 132 + tr * 8]     = v0;
            *(float4*)&Pt[(tc * 8 + j) * 132 + tr * 8 + 4] = v1;
        }
        __syncthreads();

#pragma unroll 4
        for (int j = 0; j < 128; j++) {
            float a[8];
            *(float4*)&a[0] = *(const float4*)&Pt[j * 132 + tr * 8];
            *(float4*)&a[4] = *(const float4*)&Pt[j * 132 + tr * 8 + 4];
            float4 bv = *(const float4*)&Vs[j * 68 + tc * 4];
#pragma unroll
            for (int i = 0; i < 8; i++) {
                o_acc[i][0] = fmaf(a[i], bv.x, o_acc[i][0]);
                o_acc[i][1] = fmaf(a[i], bv.y, o_acc[i][1]);
                o_acc[i][2] = fmaf(a[i], bv.z, o_acc[i][2]);
                o_acc[i][3] = fmaf(a[i], bv.w, o_acc[i][3]);
            }
        }
    }

    const int b_ = bh / NH;
    const int h  = bh % NH;
#pragma unroll
    for (int i = 0; i < 8; i++) {
        float inv = 1.0f / l_i[i];
        int row = q0 + tr * 8 + i;
        float4 v = make_float4(o_acc[i][0] * inv, o_acc[i][1] * inv,
                               o_acc[i][2] * inv, o_acc[i][3] * inv);
        *(float4*)(g_O + ((size_t)(b_ * SEQ) + row) * DIM + h * HD + tc * 4) = v;
    }
}

// ---------------------------------------------------------------------------
extern "C" void kernel_launch(void* const* d_in, const int* in_sizes, int n_in,
                              void* d_out, int out_size)
{
    const float* hs     = (const float*)d_in[0];
    const float* W_attn = (const float*)d_in[1];
    const float* b_attn = (const float*)d_in[2];
    const float* W_proj = (const float*)d_in[3];
    const float* b_proj = (const float*)d_in[4];
    float* out = (float*)d_out;

    cudaFuncSetAttribute(attn_kernel,
                         cudaFuncAttributeMaxDynamicSharedMemorySize, FL_SMEM_BYTES);
    cudaFuncSetAttribute(mma_gemm<3 * DIM, 0>,
                         cudaFuncAttributeMaxDynamicSharedMemorySize, MMA_SMEM);
    cudaFuncSetAttribute(mma_gemm<DIM, 1>,
                         cudaFuncAttributeMaxDynamicSharedMemorySize, MMA_SMEM);

    // 0) weight transpose+split, activation split
    transpose_split<0><<<dim3((3 * DIM) / 32, DIM / 32), dim3(32, 8)>>>(W_attn, 3 * DIM);
    transpose_split<1><<<dim3(DIM / 32, DIM / 32),       dim3(32, 8)>>>(W_proj, DIM);
    split_act<0><<<MTOT, 256>>>(hs);

    // 1) QKV projection (HMMA mma.sync), scattered into per-head layout
    mma_gemm<3 * DIM, 0><<<dim3((3 * DIM) / 128, MTOT / 128), 256, MMA_SMEM>>>(
        b_attn, nullptr);

    // 2) causal flash attention
    attn_kernel<<<dim3(SEQ / 128, NB * NH), 256, FL_SMEM_BYTES>>>();

    // 3) split attention output, then output projection
    split_act<1><<<MTOT, 256>>>(nullptr);
    mma_gemm<DIM, 1><<<dim3(DIM / 128, MTOT / 128), 256, MMA_SMEM>>>(
        b_proj, out);
}